// round 1
// baseline (speedup 1.0000x reference)
#include <cuda_runtime.h>
#include <math.h>

#define BATCH 32
#define TSTEPS 12
#define NN 512
#define HH 64
#define EE 10

// ---------------- device state (no allocations allowed) ----------------
__device__ float g_A[NN * NN];                // static graph
__device__ float g_Ad[BATCH * NN * NN];       // dynamic graphs (33.5 MB)
__device__ float g_h[BATCH * NN * HH];        // GRU state
__device__ float g_r[BATCH * NN * HH];        // reset gate
__device__ float g_Edyn[BATCH * NN * EE];     // dynamic embeddings
__device__ float g_inp[BATCH * NN * 66];
__device__ float g_u1[BATCH * NN * 66];
__device__ float g_u2[BATCH * NN * 66];
__device__ float g_cand[BATCH * NN * 66];
__device__ float g_go[BATCH * NN];

__device__ __forceinline__ float* bufsel(int s) {
    switch (s) {
        case 0: return g_inp;
        case 1: return g_u1;
        case 2: return g_u2;
        default: return g_cand;
    }
}

// ---------------- init ----------------
__global__ void zero_state() {
    int i = blockIdx.x * 256 + threadIdx.x;
    if (i < BATCH * NN * HH) g_h[i] = 0.f;
    if (i < BATCH * NN) g_go[i] = 0.f;
}

// ---------------- graph build: row of softmax(relu(E E^T)) ----------------
// static: grid = NN, DYN: grid = BATCH*NN.  256 threads, 2 cols/thread.
template <bool DYN>
__global__ void graph_build(const float* __restrict__ emb) {
    __shared__ float Es[NN * EE];
    __shared__ float red[8];
    int blk = blockIdx.x;
    int b = DYN ? (blk >> 9) : 0;
    int row = blk & (NN - 1);
    const float* E = DYN ? (g_Edyn + b * NN * EE) : emb;
    int tid = threadIdx.x;
    for (int i = tid; i < NN * EE; i += 256) Es[i] = E[i];
    __syncthreads();
    float er[EE];
#pragma unroll
    for (int j = 0; j < EE; j++) er[j] = Es[row * EE + j];
    float v0 = 0.f, v1 = 0.f;
    int c0 = tid, c1 = tid + 256;
#pragma unroll
    for (int j = 0; j < EE; j++) {
        v0 += er[j] * Es[c0 * EE + j];
        v1 += er[j] * Es[c1 * EE + j];
    }
    v0 = fmaxf(v0, 0.f);
    v1 = fmaxf(v1, 0.f);
    float m = fmaxf(v0, v1);
#pragma unroll
    for (int o = 16; o; o >>= 1) m = fmaxf(m, __shfl_xor_sync(0xffffffffu, m, o));
    if ((tid & 31) == 0) red[tid >> 5] = m;
    __syncthreads();
    m = red[0];
#pragma unroll
    for (int i = 1; i < 8; i++) m = fmaxf(m, red[i]);
    float e0 = expf(v0 - m), e1 = expf(v1 - m);
    float s = e0 + e1;
#pragma unroll
    for (int o = 16; o; o >>= 1) s += __shfl_xor_sync(0xffffffffu, s, o);
    __syncthreads();
    if ((tid & 31) == 0) red[tid >> 5] = s;
    __syncthreads();
    float tot = 0.f;
#pragma unroll
    for (int i = 0; i < 8; i++) tot += red[i];
    float inv = 1.f / tot;
    float* dst = DYN ? (g_Ad + b * NN * NN + row * NN) : (g_A + row * NN);
    dst[c0] = e0 * inv;
    dst[c1] = e1 * inv;
}

// ---------------- hypernetwork: E_dyn = NE + h @ hW + hb ----------------
__global__ void hyper_kernel(const float* __restrict__ ne,
                             const float* __restrict__ hW,
                             const float* __restrict__ hb) {
    __shared__ float Ws[HH * EE];
    int tid = threadIdx.x;
    for (int i = tid; i < HH * EE; i += 256) Ws[i] = hW[i];
    __syncthreads();
    int lr = tid >> 4, e = tid & 15;
    int row = blockIdx.x * 16 + lr;
    if (e < EE) {
        float acc = hb[e];
        const float* hp = g_h + row * HH;
#pragma unroll
        for (int j = 0; j < HH; j++) acc += hp[j] * Ws[j * EE + e];
        int n = row & (NN - 1);
        g_Edyn[row * EE + e] = ne[n * EE + e] + acc;
    }
}

// ---------------- graph apply: Out = alpha * A @ X (+ beta * Y) ----------------
// grid (NN/32, BATCH), 256 threads. Per thread: 4 rows x 3 col-groups.
template <int C, bool BA>
__global__ void graph_apply(int xsel, int ysel, int osel, float alpha, float beta) {
    __shared__ float As[32 * 32];
    __shared__ float Xs[32 * C];
    int b = blockIdx.y;
    int i0 = blockIdx.x * 32;
    const float* Ab = BA ? (g_Ad + b * NN * NN) : g_A;
    const float* Xb = bufsel(xsel) + b * NN * C;
    const float* Yb = (ysel >= 0) ? (bufsel(ysel) + b * NN * C) : nullptr;
    float* Ob = bufsel(osel) + b * NN * C;
    int tid = threadIdx.x;
    int tc = tid & 31, tr = tid >> 5;
    float acc[4][3];
#pragma unroll
    for (int r = 0; r < 4; r++) {
        acc[r][0] = 0.f; acc[r][1] = 0.f; acc[r][2] = 0.f;
    }
    for (int k0 = 0; k0 < NN; k0 += 32) {
#pragma unroll
        for (int q = 0; q < 4; q++) {
            int l = tid + q * 256;
            As[l] = Ab[(i0 + (l >> 5)) * NN + k0 + (l & 31)];
        }
        for (int l = tid; l < 32 * C; l += 256) Xs[l] = Xb[k0 * C + l];
        __syncthreads();
#pragma unroll
        for (int kk = 0; kk < 32; kk++) {
            float x0 = Xs[kk * C + tc];
            float x1 = Xs[kk * C + tc + 32];
            float x2 = (tc + 64 < C) ? Xs[kk * C + tc + 64] : 0.f;
#pragma unroll
            for (int r = 0; r < 4; r++) {
                float a = As[(tr + r * 8) * 32 + kk];
                acc[r][0] += a * x0;
                acc[r][1] += a * x1;
                acc[r][2] += a * x2;
            }
        }
        __syncthreads();
    }
#pragma unroll
    for (int r = 0; r < 4; r++) {
        int row = i0 + tr + r * 8;
#pragma unroll
        for (int j = 0; j < 3; j++) {
            int c = tc + 32 * j;
            if (c < C) {
                int o = row * C + c;
                float v = alpha * acc[r][j];
                if (Yb) v += beta * Yb[o];
                Ob[o] = v;
            }
        }
    }
}

// ---------------- gate: zr = sigmoid([inp,u1,u2] @ W + b); cand = [lead, z*h]; r saved ----------------
// 32 rows/block, 256 threads: each thread 8 rows x 2 cols (j, j+64)
template <int CIN>
__global__ void gate_kernel(const float* __restrict__ W, const float* __restrict__ bias) {
    constexpr int K = 3 * CIN;
    constexpr int LEAD = CIN - HH;
    __shared__ float Xs[32 * K];
    __shared__ float Ws[32 * 128];
    int r0 = blockIdx.x * 32;
    int tid = threadIdx.x;
    for (int l = tid; l < 32 * K; l += 256) {
        int r = l / K, k = l - r * K;
        int seg = k / CIN, c = k - seg * CIN;
        const float* src = (seg == 0) ? g_inp : (seg == 1) ? g_u1 : g_u2;
        Xs[l] = src[(r0 + r) * CIN + c];
    }
    int j = tid & 63, rg = tid >> 6;  // 4 row groups, rows rg + 4*i
    float acc[8][2];
#pragma unroll
    for (int i = 0; i < 8; i++) { acc[i][0] = 0.f; acc[i][1] = 0.f; }
    for (int k0 = 0; k0 < K; k0 += 32) {
        int kt = min(32, K - k0);
        __syncthreads();
        for (int l = tid; l < kt * 128; l += 256) Ws[l] = W[k0 * 128 + l];
        __syncthreads();
        for (int kk = 0; kk < kt; kk++) {
            float w0 = Ws[kk * 128 + j];
            float w1 = Ws[kk * 128 + j + 64];
#pragma unroll
            for (int i = 0; i < 8; i++) {
                float xv = Xs[(rg + 4 * i) * K + k0 + kk];
                acc[i][0] += xv * w0;
                acc[i][1] += xv * w1;
            }
        }
    }
    float b0 = bias[j], b1 = bias[j + 64];
#pragma unroll
    for (int i = 0; i < 8; i++) {
        int row = r0 + rg + 4 * i;
        float z = 1.f / (1.f + expf(-(acc[i][0] + b0)));
        float rr = 1.f / (1.f + expf(-(acc[i][1] + b1)));
        g_cand[row * CIN + LEAD + j] = z * g_h[row * HH + j];
        g_r[row * HH + j] = rr;
        if (j < LEAD) g_cand[row * CIN + j] = g_inp[row * CIN + j];
    }
}

// ---------------- update: hc = tanh([cand,u1,u2] @ W + b); h = r*h + (1-r)*hc; (dec) go = h@pW+pb ----------------
// 32 rows/block, 256 threads: each thread 4 rows x 2 cols (j, j+32). One warp owns a full 64-col row set.
template <int CIN, bool DEC>
__global__ void upd_kernel(const float* __restrict__ W, const float* __restrict__ bias,
                           const float* __restrict__ projW, const float* __restrict__ projb,
                           float* __restrict__ out, int t) {
    constexpr int K = 3 * CIN;
    __shared__ float Xs[32 * K];
    __shared__ float Ws[32 * 64];
    int r0 = blockIdx.x * 32;
    int tid = threadIdx.x;
    for (int l = tid; l < 32 * K; l += 256) {
        int r = l / K, k = l - r * K;
        int seg = k / CIN, c = k - seg * CIN;
        const float* src = (seg == 0) ? g_cand : (seg == 1) ? g_u1 : g_u2;
        Xs[l] = src[(r0 + r) * CIN + c];
    }
    int j = tid & 31, rg = tid >> 5;  // 8 row groups, rows rg + 8*i
    float acc[4][2];
#pragma unroll
    for (int i = 0; i < 4; i++) { acc[i][0] = 0.f; acc[i][1] = 0.f; }
    for (int k0 = 0; k0 < K; k0 += 32) {
        int kt = min(32, K - k0);
        __syncthreads();
        for (int l = tid; l < kt * 64; l += 256) Ws[l] = W[k0 * 64 + l];
        __syncthreads();
        for (int kk = 0; kk < kt; kk++) {
            float w0 = Ws[kk * 64 + j];
            float w1 = Ws[kk * 64 + j + 32];
#pragma unroll
            for (int i = 0; i < 4; i++) {
                float xv = Xs[(rg + 8 * i) * K + k0 + kk];
                acc[i][0] += xv * w0;
                acc[i][1] += xv * w1;
            }
        }
    }
    float b0 = bias[j], b1 = bias[j + 32];
    float pw0 = DEC ? projW[j] : 0.f;
    float pw1 = DEC ? projW[j + 32] : 0.f;
#pragma unroll
    for (int i = 0; i < 4; i++) {
        int row = r0 + rg + 8 * i;
        float hc0 = tanhf(acc[i][0] + b0);
        float hc1 = tanhf(acc[i][1] + b1);
        float rr0 = g_r[row * HH + j], rr1 = g_r[row * HH + j + 32];
        float h0 = g_h[row * HH + j], h1 = g_h[row * HH + j + 32];
        float hn0 = rr0 * h0 + (1.f - rr0) * hc0;
        float hn1 = rr1 * h1 + (1.f - rr1) * hc1;
        g_h[row * HH + j] = hn0;
        g_h[row * HH + j + 32] = hn1;
        if (DEC) {
            float p = hn0 * pw0 + hn1 * pw1;
#pragma unroll
            for (int o = 16; o; o >>= 1) p += __shfl_xor_sync(0xffffffffu, p, o);
            if (j == 0) {
                float go = p + projb[0];
                g_go[row] = go;
                int b = row >> 9, n = row & (NN - 1);
                out[(b * TSTEPS + t) * NN + n] = go;
            }
        }
    }
}

// ---------------- input builders ----------------
__global__ void enc_build_inp(const float* __restrict__ x, int t) {
    int i = blockIdx.x * 256 + threadIdx.x;
    if (i >= BATCH * NN * 65) return;
    int row = i / 65, c = i - row * 65;
    float v;
    if (c == 0) {
        int b = row >> 9, n = row & (NN - 1);
        v = x[(b * TSTEPS + t) * NN + n];
    } else {
        v = g_h[row * HH + (c - 1)];
    }
    g_inp[i] = v;
}

__global__ void dec_build_inp(const float* __restrict__ ycov, int t) {
    int i = blockIdx.x * 256 + threadIdx.x;
    if (i >= BATCH * NN * 66) return;
    int row = i / 66, c = i - row * 66;
    float v;
    if (c == 0) {
        v = g_go[row];
    } else if (c == 1) {
        int b = row >> 9, n = row & (NN - 1);
        v = ycov[(b * TSTEPS + t) * NN + n];
    } else {
        v = g_h[row * HH + (c - 2)];
    }
    g_inp[i] = v;
}

// ---------------- launch ----------------
extern "C" void kernel_launch(void* const* d_in, const int* in_sizes, int n_in,
                              void* d_out, int out_size) {
    const float* x    = (const float*)d_in[0];
    const float* ycov = (const float*)d_in[1];
    const float* ne   = (const float*)d_in[2];
    const float* egW  = (const float*)d_in[3];
    const float* egb  = (const float*)d_in[4];
    const float* euW  = (const float*)d_in[5];
    const float* eub  = (const float*)d_in[6];
    const float* dgW  = (const float*)d_in[7];
    const float* dgb  = (const float*)d_in[8];
    const float* duW  = (const float*)d_in[9];
    const float* dub  = (const float*)d_in[10];
    const float* pW   = (const float*)d_in[11];
    const float* pb   = (const float*)d_in[12];
    const float* hW   = (const float*)d_in[13];
    const float* hb   = (const float*)d_in[14];
    float* out = (float*)d_out;

    zero_state<<<(BATCH * NN * HH + 255) / 256, 256>>>();
    graph_build<false><<<NN, 256>>>(ne);

    dim3 ggrid(NN / 32, BATCH);
    // encoder
    for (int t = 0; t < TSTEPS; t++) {
        enc_build_inp<<<(BATCH * NN * 65 + 255) / 256, 256>>>(x, t);
        graph_apply<65, false><<<ggrid, 256>>>(0, -1, 1, 1.f, 0.f);   // u1 = A @ inp
        graph_apply<65, false><<<ggrid, 256>>>(1, 0, 2, 2.f, -1.f);   // u2 = 2A@u1 - inp
        gate_kernel<65><<<BATCH * NN / 32, 256>>>(egW, egb);
        graph_apply<65, false><<<ggrid, 256>>>(3, -1, 1, 1.f, 0.f);   // u1 = A @ cand
        graph_apply<65, false><<<ggrid, 256>>>(1, 3, 2, 2.f, -1.f);   // u2 = 2A@u1 - cand
        upd_kernel<65, false><<<BATCH * NN / 32, 256>>>(euW, eub, nullptr, nullptr, nullptr, 0);
    }
    // dynamic graph
    hyper_kernel<<<BATCH * NN / 16, 256>>>(ne, hW, hb);
    graph_build<true><<<BATCH * NN, 256>>>(nullptr);
    // decoder
    for (int t = 0; t < TSTEPS; t++) {
        dec_build_inp<<<(BATCH * NN * 66 + 255) / 256, 256>>>(ycov, t);
        graph_apply<66, true><<<ggrid, 256>>>(0, -1, 1, 1.f, 0.f);
        graph_apply<66, true><<<ggrid, 256>>>(1, 0, 2, 2.f, -1.f);
        gate_kernel<66><<<BATCH * NN / 32, 256>>>(dgW, dgb);
        graph_apply<66, true><<<ggrid, 256>>>(3, -1, 1, 1.f, 0.f);
        graph_apply<66, true><<<ggrid, 256>>>(1, 3, 2, 2.f, -1.f);
        upd_kernel<66, true><<<BATCH * NN / 32, 256>>>(duW, dub, pW, pb, out, t);
    }
}

// round 2
// speedup vs baseline: 1.3392x; 1.3392x over previous
#include <cuda_runtime.h>
#include <math.h>

#define BATCH 32
#define TSTEPS 12
#define NN 512
#define HH 64
#define EE 10

// ---------------- device state (no allocations allowed) ----------------
__device__ float g_A[NN * NN];                // static graph
__device__ float g_Ad[BATCH * NN * NN];       // dynamic graphs (33.5 MB)
__device__ float g_h[BATCH * NN * HH];        // GRU state (main 64 cols)
__device__ float g_zh[BATCH * NN * HH];       // z * state (cand main part)
__device__ float g_r[BATCH * NN * HH];        // reset gate
__device__ float g_u1m[BATCH * NN * HH];      // A @ main
__device__ float g_u2m[BATCH * NN * HH];      // 2A@u1 - main
__device__ float g_y1[BATCH * NN * 2];        // A @ lead
__device__ float g_y2[BATCH * NN * 2];        // A @ y1
__device__ float g_Edyn[BATCH * NN * EE];     // dynamic embeddings
__device__ float g_go[BATCH * NN];            // decoder output feedback

__device__ __forceinline__ float* buf64(int s) {
    switch (s) {
        case 0: return g_h;
        case 1: return g_zh;
        case 2: return g_u1m;
        default: return g_u2m;
    }
}

// ---------------- init ----------------
__global__ void zero_state() {
    int i = blockIdx.x * 256 + threadIdx.x;
    if (i < BATCH * NN * HH) g_h[i] = 0.f;
    if (i < BATCH * NN) g_go[i] = 0.f;
}

// ---------------- graph build: row of softmax(relu(E E^T)) ----------------
template <bool DYN>
__global__ void graph_build(const float* __restrict__ emb) {
    __shared__ float Es[NN * EE];
    __shared__ float red[8];
    int blk = blockIdx.x;
    int b = DYN ? (blk >> 9) : 0;
    int row = blk & (NN - 1);
    const float* E = DYN ? (g_Edyn + b * NN * EE) : emb;
    int tid = threadIdx.x;
    for (int i = tid; i < NN * EE; i += 256) Es[i] = E[i];
    __syncthreads();
    float er[EE];
#pragma unroll
    for (int j = 0; j < EE; j++) er[j] = Es[row * EE + j];
    float v0 = 0.f, v1 = 0.f;
    int c0 = tid, c1 = tid + 256;
#pragma unroll
    for (int j = 0; j < EE; j++) {
        v0 += er[j] * Es[c0 * EE + j];
        v1 += er[j] * Es[c1 * EE + j];
    }
    v0 = fmaxf(v0, 0.f);
    v1 = fmaxf(v1, 0.f);
    float m = fmaxf(v0, v1);
#pragma unroll
    for (int o = 16; o; o >>= 1) m = fmaxf(m, __shfl_xor_sync(0xffffffffu, m, o));
    if ((tid & 31) == 0) red[tid >> 5] = m;
    __syncthreads();
    m = red[0];
#pragma unroll
    for (int i = 1; i < 8; i++) m = fmaxf(m, red[i]);
    float e0 = expf(v0 - m), e1 = expf(v1 - m);
    float s = e0 + e1;
#pragma unroll
    for (int o = 16; o; o >>= 1) s += __shfl_xor_sync(0xffffffffu, s, o);
    __syncthreads();
    if ((tid & 31) == 0) red[tid >> 5] = s;
    __syncthreads();
    float tot = 0.f;
#pragma unroll
    for (int i = 0; i < 8; i++) tot += red[i];
    float inv = 1.f / tot;
    float* dst = DYN ? (g_Ad + (size_t)b * NN * NN + (size_t)row * NN) : (g_A + row * NN);
    dst[c0] = e0 * inv;
    dst[c1] = e1 * inv;
}

// ---------------- hypernetwork: E_dyn = NE + h @ hW + hb ----------------
__global__ void hyper_kernel(const float* __restrict__ ne,
                             const float* __restrict__ hW,
                             const float* __restrict__ hb) {
    __shared__ float Ws[HH * EE];
    int tid = threadIdx.x;
    for (int i = tid; i < HH * EE; i += 256) Ws[i] = hW[i];
    __syncthreads();
    int lr = tid >> 4, e = tid & 15;
    int row = blockIdx.x * 16 + lr;
    if (e < EE) {
        float acc = hb[e];
        const float* hp = g_h + row * HH;
#pragma unroll
        for (int j = 0; j < HH; j++) acc += hp[j] * Ws[j * EE + e];
        int n = row & (NN - 1);
        g_Edyn[row * EE + e] = ne[n * EE + e] + acc;
    }
}

// ---------------- lead mat-vec: y = A @ lead (L = 1 or 2 columns) ----------------
// MODE 0: lead from enc x; MODE 1: lead = [go, ycov]; MODE 2: lead = g_y1
// grid (8, BATCH), 256 threads. Warp per 8 rows (serial), lane-split over k.
template <int L, bool BA, int MODE>
__global__ void lead_mv(const float* __restrict__ xsrc, int t, int osel) {
    __shared__ float xs[NN * L];
    int b = blockIdx.y;
    int r0 = blockIdx.x * 64;
    const float* Ab = BA ? (g_Ad + (size_t)b * NN * NN) : g_A;
    int tid = threadIdx.x;
    for (int i = tid; i < NN * L; i += 256) {
        int k = i / L, c = i - (i / L) * L;
        float v;
        if (MODE == 0) v = xsrc[(b * TSTEPS + t) * NN + k];
        else if (MODE == 1) v = (c == 0) ? g_go[b * NN + k] : xsrc[(b * TSTEPS + t) * NN + k];
        else v = g_y1[(b * NN + k) * L + c];
        xs[i] = v;
    }
    __syncthreads();
    int w = tid >> 5, l = tid & 31;
    float* dst = osel ? g_y2 : g_y1;
#pragma unroll
    for (int rr = 0; rr < 8; rr++) {
        int row = r0 + w * 8 + rr;
        float acc0 = 0.f, acc1 = 0.f;
#pragma unroll
        for (int j = 0; j < 16; j++) {
            int k = l + 32 * j;
            float a = Ab[(size_t)row * NN + k];
            acc0 += a * xs[k * L];
            if (L == 2) acc1 += a * xs[k * L + 1];
        }
#pragma unroll
        for (int o = 16; o; o >>= 1) acc0 += __shfl_xor_sync(0xffffffffu, acc0, o);
        if (L == 2) {
#pragma unroll
            for (int o = 16; o; o >>= 1) acc1 += __shfl_xor_sync(0xffffffffu, acc1, o);
        }
        if (l == 0) {
            dst[(b * NN + row) * L] = acc0;
            if (L == 2) dst[(b * NN + row) * L + 1] = acc1;
        }
    }
}

// ---------------- main graph apply (C = 64): Out = alpha * A @ X (+ beta * Y) ----------------
// grid (8, BATCH), 256 threads. 64-row tile; per thread 8 rows x 2 cols.
// A tile loaded row-major; read as broadcast float4 along kk (conflict-free).
template <bool BA>
__global__ void __launch_bounds__(256) ga64(int xsel, int ysel, int osel, float alpha, float beta) {
    __shared__ float As[64 * 32];
    __shared__ float Xs[32 * 64];
    int b = blockIdx.y;
    int i0 = blockIdx.x * 64;
    const float* Ab = BA ? (g_Ad + (size_t)b * NN * NN) : g_A;
    const float* Xb = buf64(xsel) + b * NN * HH;
    const float* Yb = (ysel >= 0) ? (buf64(ysel) + b * NN * HH) : nullptr;
    float* Ob = buf64(osel) + b * NN * HH;
    int tid = threadIdx.x;
    int tc = tid & 31, tr = tid >> 5;
    float acc[8][2];
#pragma unroll
    for (int r = 0; r < 8; r++) { acc[r][0] = 0.f; acc[r][1] = 0.f; }
    for (int k0 = 0; k0 < NN; k0 += 32) {
#pragma unroll
        for (int q = 0; q < 8; q++) {
            int ll = tid + q * 256;
            As[ll] = Ab[(size_t)(i0 + (ll >> 5)) * NN + k0 + (ll & 31)];
        }
#pragma unroll
        for (int q = 0; q < 8; q++) {
            int ll = tid + q * 256;
            Xs[ll] = Xb[k0 * HH + ll];
        }
        __syncthreads();
#pragma unroll
        for (int kk = 0; kk < 32; kk += 4) {
            float4 a[8];
#pragma unroll
            for (int r = 0; r < 8; r++)
                a[r] = *(const float4*)&As[(tr * 8 + r) * 32 + kk];
#pragma unroll
            for (int q = 0; q < 4; q++) {
                float x0 = Xs[(kk + q) * 64 + tc];
                float x1 = Xs[(kk + q) * 64 + tc + 32];
#pragma unroll
                for (int r = 0; r < 8; r++) {
                    float av = (q == 0) ? a[r].x : (q == 1) ? a[r].y : (q == 2) ? a[r].z : a[r].w;
                    acc[r][0] += av * x0;
                    acc[r][1] += av * x1;
                }
            }
        }
        __syncthreads();
    }
#pragma unroll
    for (int r = 0; r < 8; r++) {
        int row = i0 + tr * 8 + r;
        int o0 = row * HH + tc;
        float v0 = alpha * acc[r][0];
        float v1 = alpha * acc[r][1];
        if (Yb) { v0 += beta * Yb[o0]; v1 += beta * Yb[o0 + 32]; }
        Ob[o0] = v0;
        Ob[o0 + 32] = v1;
    }
}

// ---------------- Xs assembly helper (shared by gate/upd) ----------------
template <int CIN, bool ENC, bool UPD>
__device__ __forceinline__ void load_xs(float* Xs, int r0, const float* __restrict__ xsrc, int t) {
    constexpr int K = 3 * CIN;
    constexpr int L = CIN - HH;
    int tid = threadIdx.x;
    for (int i = tid; i < 32 * K; i += 256) {
        int r = i / K, k = i - r * K;
        int seg = k / CIN, c = k - seg * CIN;
        int row = r0 + r, b = row >> 9, n = row & (NN - 1);
        float v;
        if (c < L) {
            float x0;
            if (ENC) x0 = xsrc[(b * TSTEPS + t) * NN + n];
            else x0 = (c == 0) ? g_go[row] : xsrc[(b * TSTEPS + t) * NN + n];
            if (seg == 0) v = x0;
            else if (seg == 1) v = g_y1[row * L + c];
            else v = 2.f * g_y2[row * L + c] - x0;
        } else {
            int cm = c - L;
            const float* src = (seg == 0) ? (UPD ? g_zh : g_h) : (seg == 1) ? g_u1m : g_u2m;
            v = src[row * HH + cm];
        }
        Xs[i] = v;
    }
}

// ---------------- gate: zr = sigmoid(X @ W + b); zh = z*h; r saved ----------------
// 32 rows/block, 256 threads: each thread 8 rows x 2 cols (j, j+64)
template <int CIN, bool ENC>
__global__ void gate_kernel(const float* __restrict__ W, const float* __restrict__ bias,
                            const float* __restrict__ xsrc, int t) {
    constexpr int K = 3 * CIN;
    __shared__ float Xs[32 * K];
    __shared__ float Ws[32 * 128];
    int r0 = blockIdx.x * 32;
    int tid = threadIdx.x;
    load_xs<CIN, ENC, false>(Xs, r0, xsrc, t);
    int j = tid & 63, rg = tid >> 6;
    float acc[8][2];
#pragma unroll
    for (int i = 0; i < 8; i++) { acc[i][0] = 0.f; acc[i][1] = 0.f; }
    for (int k0 = 0; k0 < K; k0 += 32) {
        int kt = min(32, K - k0);
        __syncthreads();
        for (int l = tid; l < kt * 128; l += 256) Ws[l] = W[k0 * 128 + l];
        __syncthreads();
        for (int kk = 0; kk < kt; kk++) {
            float w0 = Ws[kk * 128 + j];
            float w1 = Ws[kk * 128 + j + 64];
#pragma unroll
            for (int i = 0; i < 8; i++) {
                float xv = Xs[(rg + 4 * i) * K + k0 + kk];
                acc[i][0] += xv * w0;
                acc[i][1] += xv * w1;
            }
        }
    }
    float b0 = bias[j], b1 = bias[j + 64];
#pragma unroll
    for (int i = 0; i < 8; i++) {
        int row = r0 + rg + 4 * i;
        float z = 1.f / (1.f + expf(-(acc[i][0] + b0)));
        float rr = 1.f / (1.f + expf(-(acc[i][1] + b1)));
        g_zh[row * HH + j] = z * g_h[row * HH + j];
        g_r[row * HH + j] = rr;
    }
}

// ---------------- update: hc = tanh(X @ W + b); h = r*h + (1-r)*hc; (dec) go = h@pW+pb ----------------
template <int CIN, bool DEC>
__global__ void upd_kernel(const float* __restrict__ W, const float* __restrict__ bias,
                           const float* __restrict__ projW, const float* __restrict__ projb,
                           float* __restrict__ out, const float* __restrict__ xsrc, int t) {
    constexpr int K = 3 * CIN;
    __shared__ float Xs[32 * K];
    __shared__ float Ws[32 * 64];
    int r0 = blockIdx.x * 32;
    int tid = threadIdx.x;
    load_xs<CIN, !DEC, true>(Xs, r0, xsrc, t);
    int j = tid & 31, rg = tid >> 5;
    float acc[4][2];
#pragma unroll
    for (int i = 0; i < 4; i++) { acc[i][0] = 0.f; acc[i][1] = 0.f; }
    for (int k0 = 0; k0 < K; k0 += 32) {
        int kt = min(32, K - k0);
        __syncthreads();
        for (int l = tid; l < kt * 64; l += 256) Ws[l] = W[k0 * 64 + l];
        __syncthreads();
        for (int kk = 0; kk < kt; kk++) {
            float w0 = Ws[kk * 64 + j];
            float w1 = Ws[kk * 64 + j + 32];
#pragma unroll
            for (int i = 0; i < 4; i++) {
                float xv = Xs[(rg + 8 * i) * K + k0 + kk];
                acc[i][0] += xv * w0;
                acc[i][1] += xv * w1;
            }
        }
    }
    float b0 = bias[j], b1 = bias[j + 32];
    float pw0 = DEC ? projW[j] : 0.f;
    float pw1 = DEC ? projW[j + 32] : 0.f;
#pragma unroll
    for (int i = 0; i < 4; i++) {
        int row = r0 + rg + 8 * i;
        float hc0 = tanhf(acc[i][0] + b0);
        float hc1 = tanhf(acc[i][1] + b1);
        float rr0 = g_r[row * HH + j], rr1 = g_r[row * HH + j + 32];
        float h0 = g_h[row * HH + j], h1 = g_h[row * HH + j + 32];
        float hn0 = rr0 * h0 + (1.f - rr0) * hc0;
        float hn1 = rr1 * h1 + (1.f - rr1) * hc1;
        g_h[row * HH + j] = hn0;
        g_h[row * HH + j + 32] = hn1;
        if (DEC) {
            float p = hn0 * pw0 + hn1 * pw1;
#pragma unroll
            for (int o = 16; o; o >>= 1) p += __shfl_xor_sync(0xffffffffu, p, o);
            if (j == 0) {
                float go = p + projb[0];
                g_go[row] = go;
                int b = row >> 9, n = row & (NN - 1);
                out[(b * TSTEPS + t) * NN + n] = go;
            }
        }
    }
}

// buffer selectors for ga64
#define SEL_H 0
#define SEL_ZH 1
#define SEL_U1 2
#define SEL_U2 3

// ---------------- launch ----------------
extern "C" void kernel_launch(void* const* d_in, const int* in_sizes, int n_in,
                              void* d_out, int out_size) {
    const float* x    = (const float*)d_in[0];
    const float* ycov = (const float*)d_in[1];
    const float* ne   = (const float*)d_in[2];
    const float* egW  = (const float*)d_in[3];
    const float* egb  = (const float*)d_in[4];
    const float* euW  = (const float*)d_in[5];
    const float* eub  = (const float*)d_in[6];
    const float* dgW  = (const float*)d_in[7];
    const float* dgb  = (const float*)d_in[8];
    const float* duW  = (const float*)d_in[9];
    const float* dub  = (const float*)d_in[10];
    const float* pW   = (const float*)d_in[11];
    const float* pb   = (const float*)d_in[12];
    const float* hW   = (const float*)d_in[13];
    const float* hb   = (const float*)d_in[14];
    float* out = (float*)d_out;

    zero_state<<<(BATCH * NN * HH + 255) / 256, 256>>>();
    graph_build<false><<<NN, 256>>>(ne);

    dim3 ggrid(NN / 64, BATCH);
    // encoder
    for (int t = 0; t < TSTEPS; t++) {
        lead_mv<1, false, 0><<<ggrid, 256>>>(x, t, 0);             // y1 = A @ x_lead
        lead_mv<1, false, 2><<<ggrid, 256>>>(nullptr, 0, 1);       // y2 = A @ y1
        ga64<false><<<ggrid, 256>>>(SEL_H, -1, SEL_U1, 1.f, 0.f);  // u1 = A @ h
        ga64<false><<<ggrid, 256>>>(SEL_U1, SEL_H, SEL_U2, 2.f, -1.f);
        gate_kernel<65, true><<<BATCH * NN / 32, 256>>>(egW, egb, x, t);
        ga64<false><<<ggrid, 256>>>(SEL_ZH, -1, SEL_U1, 1.f, 0.f); // u1 = A @ zh
        ga64<false><<<ggrid, 256>>>(SEL_U1, SEL_ZH, SEL_U2, 2.f, -1.f);
        upd_kernel<65, false><<<BATCH * NN / 32, 256>>>(euW, eub, nullptr, nullptr, nullptr, x, t);
    }
    // dynamic graph
    hyper_kernel<<<BATCH * NN / 16, 256>>>(ne, hW, hb);
    graph_build<true><<<BATCH * NN, 256>>>(nullptr);
    // decoder
    for (int t = 0; t < TSTEPS; t++) {
        lead_mv<2, true, 1><<<ggrid, 256>>>(ycov, t, 0);           // y1 = A_d @ [go, ycov]
        lead_mv<2, true, 2><<<ggrid, 256>>>(nullptr, 0, 1);        // y2 = A_d @ y1
        ga64<true><<<ggrid, 256>>>(SEL_H, -1, SEL_U1, 1.f, 0.f);
        ga64<true><<<ggrid, 256>>>(SEL_U1, SEL_H, SEL_U2, 2.f, -1.f);
        gate_kernel<66, false><<<BATCH * NN / 32, 256>>>(dgW, dgb, ycov, t);
        ga64<true><<<ggrid, 256>>>(SEL_ZH, -1, SEL_U1, 1.f, 0.f);
        ga64<true><<<ggrid, 256>>>(SEL_U1, SEL_ZH, SEL_U2, 2.f, -1.f);
        upd_kernel<66, true><<<BATCH * NN / 32, 256>>>(duW, dub, pW, pb, out, ycov, t);
    }
}

// round 3
// speedup vs baseline: 1.7974x; 1.3422x over previous
#include <cuda_runtime.h>
#include <math.h>
#include <stdint.h>

#define BATCH 32
#define TSTEPS 12
#define NN 512
#define HH 64
#define EE 10

// ---------------- device state (no allocations allowed) ----------------
__device__ float g_A[NN * NN];                // static graph
__device__ float g_Ad[BATCH * NN * NN];       // dynamic graphs (33.5 MB)
__device__ float g_h[BATCH * NN * HH];        // GRU state (main 64 cols)
__device__ float g_zh[BATCH * NN * HH];       // z * state (cand main part)
__device__ float g_r[BATCH * NN * HH];        // reset gate
__device__ float g_u1m[BATCH * NN * HH];      // A @ main
__device__ float g_u2m[BATCH * NN * HH];      // 2A@u1 - main
__device__ float g_y1[BATCH * NN * 2];        // A @ lead
__device__ float g_y2[BATCH * NN * 2];        // A @ y1
__device__ float g_Edyn[BATCH * NN * EE];     // dynamic embeddings
__device__ float g_go[BATCH * NN];            // decoder output feedback

__device__ __forceinline__ float* buf64(int s) {
    switch (s) {
        case 0: return g_h;
        case 1: return g_zh;
        case 2: return g_u1m;
        default: return g_u2m;
    }
}

__device__ __forceinline__ uint32_t tf32cvt(float x) {
    uint32_t r;
    asm("cvt.rna.tf32.f32 %0, %1;" : "=r"(r) : "f"(x));
    return r;
}

__device__ __forceinline__ void mma_tf32(float* d, uint32_t a0, uint32_t a1, uint32_t a2,
                                         uint32_t a3, uint32_t b0, uint32_t b1) {
    asm volatile(
        "mma.sync.aligned.m16n8k8.row.col.f32.tf32.tf32.f32 "
        "{%0,%1,%2,%3},{%4,%5,%6,%7},{%8,%9},{%0,%1,%2,%3};"
        : "+f"(d[0]), "+f"(d[1]), "+f"(d[2]), "+f"(d[3])
        : "r"(a0), "r"(a1), "r"(a2), "r"(a3), "r"(b0), "r"(b1));
}

// ---------------- init ----------------
__global__ void zero_state() {
    int i = blockIdx.x * 256 + threadIdx.x;
    if (i < BATCH * NN * HH) g_h[i] = 0.f;
    if (i < BATCH * NN) g_go[i] = 0.f;
}

// ---------------- graph build: row of softmax(relu(E E^T)) ----------------
template <bool DYN>
__global__ void graph_build(const float* __restrict__ emb) {
    __shared__ float Es[NN * EE];
    __shared__ float red[8];
    int blk = blockIdx.x;
    int b = DYN ? (blk >> 9) : 0;
    int row = blk & (NN - 1);
    const float* E = DYN ? (g_Edyn + b * NN * EE) : emb;
    int tid = threadIdx.x;
    for (int i = tid; i < NN * EE; i += 256) Es[i] = E[i];
    __syncthreads();
    float er[EE];
#pragma unroll
    for (int j = 0; j < EE; j++) er[j] = Es[row * EE + j];
    float v0 = 0.f, v1 = 0.f;
    int c0 = tid, c1 = tid + 256;
#pragma unroll
    for (int j = 0; j < EE; j++) {
        v0 += er[j] * Es[c0 * EE + j];
        v1 += er[j] * Es[c1 * EE + j];
    }
    v0 = fmaxf(v0, 0.f);
    v1 = fmaxf(v1, 0.f);
    float m = fmaxf(v0, v1);
#pragma unroll
    for (int o = 16; o; o >>= 1) m = fmaxf(m, __shfl_xor_sync(0xffffffffu, m, o));
    if ((tid & 31) == 0) red[tid >> 5] = m;
    __syncthreads();
    m = red[0];
#pragma unroll
    for (int i = 1; i < 8; i++) m = fmaxf(m, red[i]);
    float e0 = expf(v0 - m), e1 = expf(v1 - m);
    float s = e0 + e1;
#pragma unroll
    for (int o = 16; o; o >>= 1) s += __shfl_xor_sync(0xffffffffu, s, o);
    __syncthreads();
    if ((tid & 31) == 0) red[tid >> 5] = s;
    __syncthreads();
    float tot = 0.f;
#pragma unroll
    for (int i = 0; i < 8; i++) tot += red[i];
    float inv = 1.f / tot;
    float* dst = DYN ? (g_Ad + (size_t)b * NN * NN + (size_t)row * NN) : (g_A + row * NN);
    dst[c0] = e0 * inv;
    dst[c1] = e1 * inv;
}

// ---------------- hypernetwork: E_dyn = NE + h @ hW + hb ----------------
__global__ void hyper_kernel(const float* __restrict__ ne,
                             const float* __restrict__ hW,
                             const float* __restrict__ hb) {
    __shared__ float Ws[HH * EE];
    int tid = threadIdx.x;
    for (int i = tid; i < HH * EE; i += 256) Ws[i] = hW[i];
    __syncthreads();
    int lr = tid >> 4, e = tid & 15;
    int row = blockIdx.x * 16 + lr;
    if (e < EE) {
        float acc = hb[e];
        const float* hp = g_h + row * HH;
#pragma unroll
        for (int j = 0; j < HH; j++) acc += hp[j] * Ws[j * EE + e];
        int n = row & (NN - 1);
        g_Edyn[row * EE + e] = ne[n * EE + e] + acc;
    }
}

// ---------------- fused main graph apply + lead mat-vec ----------------
// blockIdx.x < 8 : tf32 mma tile: Out64 = alpha * A @ X64 (+ beta * Y64)
// blockIdx.x == 8 (if L>0): lead: ydst = A @ lead (L cols)
// LMODE 0: lead = x(t) (enc); 1: lead = [go, ycov(t)] (dec); 2: lead = g_y1
#define AS 36
#define XS 72
template <bool BA, int L, int LMODE>
__global__ void __launch_bounds__(256) ga64mma(int xsel, int ysel, int osel,
                                               float alpha, float beta,
                                               const float* __restrict__ xsrc, int t,
                                               int leaddst) {
    __shared__ float As[64 * AS];
    __shared__ float Xs[32 * XS];
    __shared__ float xsl[L > 0 ? NN * L : 1];
    int b = blockIdx.y;
    int tid = threadIdx.x;
    const float* Ab = BA ? (g_Ad + (size_t)b * NN * NN) : g_A;

    if (L > 0 && blockIdx.x == 8) {
        // ---- lead path: y = A @ lead ----
        for (int i = tid; i < NN * L; i += 256) {
            int k = i / L, c = i - (i / L) * L;
            float v;
            if (LMODE == 0) v = xsrc[(b * TSTEPS + t) * NN + k];
            else if (LMODE == 1) v = (c == 0) ? g_go[b * NN + k] : xsrc[(b * TSTEPS + t) * NN + k];
            else v = g_y1[(b * NN + k) * L + c];
            xsl[i] = v;
        }
        __syncthreads();
        int w = tid >> 5, l = tid & 31;
        float* dst = leaddst ? g_y2 : g_y1;
#pragma unroll 4
        for (int rr = 0; rr < 64; rr++) {
            int row = w * 64 + rr;
            float acc0 = 0.f, acc1 = 0.f;
#pragma unroll
            for (int j = 0; j < 16; j++) {
                int k = l + 32 * j;
                float a = Ab[(size_t)row * NN + k];
                acc0 += a * xsl[k * L];
                if (L == 2) acc1 += a * xsl[k * L + 1];
            }
#pragma unroll
            for (int o = 16; o; o >>= 1) acc0 += __shfl_xor_sync(0xffffffffu, acc0, o);
            if (L == 2) {
#pragma unroll
                for (int o = 16; o; o >>= 1) acc1 += __shfl_xor_sync(0xffffffffu, acc1, o);
            }
            if (l == 0) {
                dst[(b * NN + row) * L] = acc0;
                if (L == 2) dst[(b * NN + row) * L + 1] = acc1;
            }
        }
        return;
    }

    // ---- tf32 mma path ----
    int i0 = blockIdx.x * 64;
    const float* Xb = buf64(xsel) + b * NN * HH;
    const float* Yb = (ysel >= 0) ? (buf64(ysel) + b * NN * HH) : nullptr;
    float* Ob = buf64(osel) + b * NN * HH;
    int lane = tid & 31, w = tid >> 5;
    int gid = lane >> 2, tq = lane & 3;
    int R = (w & 3) * 16;
    int CH = (w >> 2) * 32;
    float acc[4][4];
#pragma unroll
    for (int j = 0; j < 4; j++)
#pragma unroll
        for (int c = 0; c < 4; c++) acc[j][c] = 0.f;

    for (int k0 = 0; k0 < NN; k0 += 32) {
#pragma unroll
        for (int q = 0; q < 8; q++) {
            int ll = tid + q * 256;
            int r = ll >> 5, c = ll & 31;
            As[r * AS + c] = __uint_as_float(tf32cvt(Ab[(size_t)(i0 + r) * NN + k0 + c]));
        }
#pragma unroll
        for (int q = 0; q < 8; q++) {
            int ll = tid + q * 256;
            int k = ll >> 6, n = ll & 63;
            Xs[k * XS + n] = __uint_as_float(tf32cvt(Xb[(k0 + k) * HH + n]));
        }
        __syncthreads();
#pragma unroll
        for (int ks = 0; ks < 4; ks++) {
            int kb = ks * 8;
            uint32_t a0 = __float_as_uint(As[(R + gid) * AS + kb + tq]);
            uint32_t a1 = __float_as_uint(As[(R + gid + 8) * AS + kb + tq]);
            uint32_t a2 = __float_as_uint(As[(R + gid) * AS + kb + tq + 4]);
            uint32_t a3 = __float_as_uint(As[(R + gid + 8) * AS + kb + tq + 4]);
#pragma unroll
            for (int j = 0; j < 4; j++) {
                int nb = CH + j * 8;
                uint32_t b0 = __float_as_uint(Xs[(kb + tq) * XS + nb + gid]);
                uint32_t b1 = __float_as_uint(Xs[(kb + tq + 4) * XS + nb + gid]);
                mma_tf32(acc[j], a0, a1, a2, a3, b0, b1);
            }
        }
        __syncthreads();
    }
#pragma unroll
    for (int j = 0; j < 4; j++) {
        int nb = CH + j * 8;
        int col = nb + 2 * tq;
        int row0 = i0 + R + gid;
        int row1 = row0 + 8;
        int o0 = row0 * HH + col;
        int o1 = row1 * HH + col;
        float v00 = alpha * acc[j][0], v01 = alpha * acc[j][1];
        float v10 = alpha * acc[j][2], v11 = alpha * acc[j][3];
        if (Yb) {
            v00 += beta * Yb[o0]; v01 += beta * Yb[o0 + 1];
            v10 += beta * Yb[o1]; v11 += beta * Yb[o1 + 1];
        }
        Ob[o0] = v00; Ob[o0 + 1] = v01;
        Ob[o1] = v10; Ob[o1 + 1] = v11;
    }
}

// ---------------- Xs assembly helper (shared by gate/upd) ----------------
template <int CIN, bool ENC, bool UPD>
__device__ __forceinline__ void load_xs(float* Xs, int r0, const float* __restrict__ xsrc, int t) {
    constexpr int K = 3 * CIN;
    constexpr int L = CIN - HH;
    int tid = threadIdx.x;
    for (int i = tid; i < 32 * K; i += 256) {
        int r = i / K, k = i - r * K;
        int seg = k / CIN, c = k - seg * CIN;
        int row = r0 + r, b = row >> 9, n = row & (NN - 1);
        float v;
        if (c < L) {
            float x0;
            if (ENC) x0 = xsrc[(b * TSTEPS + t) * NN + n];
            else x0 = (c == 0) ? g_go[row] : xsrc[(b * TSTEPS + t) * NN + n];
            if (seg == 0) v = x0;
            else if (seg == 1) v = g_y1[row * L + c];
            else v = 2.f * g_y2[row * L + c] - x0;
        } else {
            int cm = c - L;
            const float* src = (seg == 0) ? (UPD ? g_zh : g_h) : (seg == 1) ? g_u1m : g_u2m;
            v = src[row * HH + cm];
        }
        Xs[i] = v;
    }
}

// ---------------- gate: zr = sigmoid(X @ W + b); zh = z*h; r saved ----------------
template <int CIN, bool ENC>
__global__ void gate_kernel(const float* __restrict__ W, const float* __restrict__ bias,
                            const float* __restrict__ xsrc, int t) {
    constexpr int K = 3 * CIN;
    __shared__ float Xs[32 * K];
    __shared__ float Ws[32 * 128];
    int r0 = blockIdx.x * 32;
    int tid = threadIdx.x;
    load_xs<CIN, ENC, false>(Xs, r0, xsrc, t);
    int j = tid & 63, rg = tid >> 6;
    float acc[8][2];
#pragma unroll
    for (int i = 0; i < 8; i++) { acc[i][0] = 0.f; acc[i][1] = 0.f; }
    for (int k0 = 0; k0 < K; k0 += 32) {
        int kt = min(32, K - k0);
        __syncthreads();
        for (int l = tid; l < kt * 128; l += 256) Ws[l] = W[k0 * 128 + l];
        __syncthreads();
        for (int kk = 0; kk < kt; kk++) {
            float w0 = Ws[kk * 128 + j];
            float w1 = Ws[kk * 128 + j + 64];
#pragma unroll
            for (int i = 0; i < 8; i++) {
                float xv = Xs[(rg + 4 * i) * K + k0 + kk];
                acc[i][0] += xv * w0;
                acc[i][1] += xv * w1;
            }
        }
    }
    float b0 = bias[j], b1 = bias[j + 64];
#pragma unroll
    for (int i = 0; i < 8; i++) {
        int row = r0 + rg + 4 * i;
        float z = 1.f / (1.f + expf(-(acc[i][0] + b0)));
        float rr = 1.f / (1.f + expf(-(acc[i][1] + b1)));
        g_zh[row * HH + j] = z * g_h[row * HH + j];
        g_r[row * HH + j] = rr;
    }
}

// ---------------- update: hc = tanh(X @ W + b); h = r*h + (1-r)*hc; (dec) go = h@pW+pb ----------------
template <int CIN, bool DEC>
__global__ void upd_kernel(const float* __restrict__ W, const float* __restrict__ bias,
                           const float* __restrict__ projW, const float* __restrict__ projb,
                           float* __restrict__ out, const float* __restrict__ xsrc, int t) {
    constexpr int K = 3 * CIN;
    __shared__ float Xs[32 * K];
    __shared__ float Ws[32 * 64];
    int r0 = blockIdx.x * 32;
    int tid = threadIdx.x;
    load_xs<CIN, !DEC, true>(Xs, r0, xsrc, t);
    int j = tid & 31, rg = tid >> 5;
    float acc[4][2];
#pragma unroll
    for (int i = 0; i < 4; i++) { acc[i][0] = 0.f; acc[i][1] = 0.f; }
    for (int k0 = 0; k0 < K; k0 += 32) {
        int kt = min(32, K - k0);
        __syncthreads();
        for (int l = tid; l < kt * 64; l += 256) Ws[l] = W[k0 * 64 + l];
        __syncthreads();
        for (int kk = 0; kk < kt; kk++) {
            float w0 = Ws[kk * 64 + j];
            float w1 = Ws[kk * 64 + j + 32];
#pragma unroll
            for (int i = 0; i < 4; i++) {
                float xv = Xs[(rg + 8 * i) * K + k0 + kk];
                acc[i][0] += xv * w0;
                acc[i][1] += xv * w1;
            }
        }
    }
    float b0 = bias[j], b1 = bias[j + 32];
    float pw0 = DEC ? projW[j] : 0.f;
    float pw1 = DEC ? projW[j + 32] : 0.f;
#pragma unroll
    for (int i = 0; i < 4; i++) {
        int row = r0 + rg + 8 * i;
        float hc0 = tanhf(acc[i][0] + b0);
        float hc1 = tanhf(acc[i][1] + b1);
        float rr0 = g_r[row * HH + j], rr1 = g_r[row * HH + j + 32];
        float h0 = g_h[row * HH + j], h1 = g_h[row * HH + j + 32];
        float hn0 = rr0 * h0 + (1.f - rr0) * hc0;
        float hn1 = rr1 * h1 + (1.f - rr1) * hc1;
        g_h[row * HH + j] = hn0;
        g_h[row * HH + j + 32] = hn1;
        if (DEC) {
            float p = hn0 * pw0 + hn1 * pw1;
#pragma unroll
            for (int o = 16; o; o >>= 1) p += __shfl_xor_sync(0xffffffffu, p, o);
            if (j == 0) {
                float go = p + projb[0];
                g_go[row] = go;
                int b = row >> 9, n = row & (NN - 1);
                out[(b * TSTEPS + t) * NN + n] = go;
            }
        }
    }
}

#define SEL_H 0
#define SEL_ZH 1
#define SEL_U1 2
#define SEL_U2 3

// ---------------- launch ----------------
extern "C" void kernel_launch(void* const* d_in, const int* in_sizes, int n_in,
                              void* d_out, int out_size) {
    const float* x    = (const float*)d_in[0];
    const float* ycov = (const float*)d_in[1];
    const float* ne   = (const float*)d_in[2];
    const float* egW  = (const float*)d_in[3];
    const float* egb  = (const float*)d_in[4];
    const float* euW  = (const float*)d_in[5];
    const float* eub  = (const float*)d_in[6];
    const float* dgW  = (const float*)d_in[7];
    const float* dgb  = (const float*)d_in[8];
    const float* duW  = (const float*)d_in[9];
    const float* dub  = (const float*)d_in[10];
    const float* pW   = (const float*)d_in[11];
    const float* pb   = (const float*)d_in[12];
    const float* hW   = (const float*)d_in[13];
    const float* hb   = (const float*)d_in[14];
    float* out = (float*)d_out;

    zero_state<<<(BATCH * NN * HH + 255) / 256, 256>>>();
    graph_build<false><<<NN, 256>>>(ne);

    dim3 g9(9, BATCH), g8(8, BATCH);
    // encoder
    for (int t = 0; t < TSTEPS; t++) {
        ga64mma<false, 1, 0><<<g9, 256>>>(SEL_H, -1, SEL_U1, 1.f, 0.f, x, t, 0);      // u1=A@h ; y1=A@x
        ga64mma<false, 1, 2><<<g9, 256>>>(SEL_U1, SEL_H, SEL_U2, 2.f, -1.f, x, t, 1); // u2    ; y2=A@y1
        gate_kernel<65, true><<<BATCH * NN / 32, 256>>>(egW, egb, x, t);
        ga64mma<false, 0, 0><<<g8, 256>>>(SEL_ZH, -1, SEL_U1, 1.f, 0.f, nullptr, 0, 0);
        ga64mma<false, 0, 0><<<g8, 256>>>(SEL_U1, SEL_ZH, SEL_U2, 2.f, -1.f, nullptr, 0, 0);
        upd_kernel<65, false><<<BATCH * NN / 32, 256>>>(euW, eub, nullptr, nullptr, nullptr, x, t);
    }
    // dynamic graph
    hyper_kernel<<<BATCH * NN / 16, 256>>>(ne, hW, hb);
    graph_build<true><<<BATCH * NN, 256>>>(nullptr);
    // decoder
    for (int t = 0; t < TSTEPS; t++) {
        ga64mma<true, 2, 1><<<g9, 256>>>(SEL_H, -1, SEL_U1, 1.f, 0.f, ycov, t, 0);
        ga64mma<true, 2, 2><<<g9, 256>>>(SEL_U1, SEL_H, SEL_U2, 2.f, -1.f, ycov, t, 1);
        gate_kernel<66, false><<<BATCH * NN / 32, 256>>>(dgW, dgb, ycov, t);
        ga64mma<true, 0, 0><<<g8, 256>>>(SEL_ZH, -1, SEL_U1, 1.f, 0.f, nullptr, 0, 0);
        ga64mma<true, 0, 0><<<g8, 256>>>(SEL_U1, SEL_ZH, SEL_U2, 2.f, -1.f, nullptr, 0, 0);
        upd_kernel<66, true><<<BATCH * NN / 32, 256>>>(duW, dub, pW, pb, out, ycov, t);
    }
}

// round 4
// speedup vs baseline: 2.0659x; 1.1494x over previous
#include <cuda_runtime.h>
#include <math.h>
#include <stdint.h>

#define BATCH 32
#define TSTEPS 12
#define NN 512
#define HH 64
#define EE 10

// ---------------- device state (no allocations allowed) ----------------
__device__ float g_A[NN * NN];                // static graph (tf32-rounded)
__device__ float g_Ad[BATCH * NN * NN];       // dynamic graphs (tf32-rounded)
__device__ float g_h[BATCH * NN * HH];        // GRU state
__device__ float g_zh[BATCH * NN * HH];       // z * state
__device__ float g_r[BATCH * NN * HH];        // reset gate
__device__ float g_u1m[BATCH * NN * HH];      // A @ main
__device__ float g_u2m[BATCH * NN * HH];      // 2A@u1 - main
__device__ float g_y1[BATCH * NN * 2];        // A @ lead
__device__ float g_y2[BATCH * NN * 2];        // A @ y1
__device__ float g_Edyn[BATCH * NN * EE];     // dynamic embeddings
__device__ float g_go[BATCH * NN];            // decoder output feedback

__device__ __forceinline__ float* buf64(int s) {
    switch (s) {
        case 0: return g_h;
        case 1: return g_zh;
        case 2: return g_u1m;
        default: return g_u2m;
    }
}

__device__ __forceinline__ uint32_t tf32cvt(float x) {
    uint32_t r;
    asm("cvt.rna.tf32.f32 %0, %1;" : "=r"(r) : "f"(x));
    return r;
}

__device__ __forceinline__ void mma_tf32(float* d, uint32_t a0, uint32_t a1, uint32_t a2,
                                         uint32_t a3, uint32_t b0, uint32_t b1) {
    asm volatile(
        "mma.sync.aligned.m16n8k8.row.col.f32.tf32.tf32.f32 "
        "{%0,%1,%2,%3},{%4,%5,%6,%7},{%8,%9},{%0,%1,%2,%3};"
        : "+f"(d[0]), "+f"(d[1]), "+f"(d[2]), "+f"(d[3])
        : "r"(a0), "r"(a1), "r"(a2), "r"(a3), "r"(b0), "r"(b1));
}

// ---------------- init ----------------
__global__ void zero_state() {
    int i = blockIdx.x * 256 + threadIdx.x;
    if (i < BATCH * NN * HH) g_h[i] = 0.f;
    if (i < BATCH * NN) g_go[i] = 0.f;
}

// ---------------- graph build: row of softmax(relu(E E^T)), stored tf32-rounded ----------------
template <bool DYN>
__global__ void graph_build(const float* __restrict__ emb) {
    __shared__ float Es[NN * EE];
    __shared__ float red[8];
    int blk = blockIdx.x;
    int b = DYN ? (blk >> 9) : 0;
    int row = blk & (NN - 1);
    const float* E = DYN ? (g_Edyn + b * NN * EE) : emb;
    int tid = threadIdx.x;
    for (int i = tid; i < NN * EE; i += 256) Es[i] = E[i];
    __syncthreads();
    float er[EE];
#pragma unroll
    for (int j = 0; j < EE; j++) er[j] = Es[row * EE + j];
    float v0 = 0.f, v1 = 0.f;
    int c0 = tid, c1 = tid + 256;
#pragma unroll
    for (int j = 0; j < EE; j++) {
        v0 += er[j] * Es[c0 * EE + j];
        v1 += er[j] * Es[c1 * EE + j];
    }
    v0 = fmaxf(v0, 0.f);
    v1 = fmaxf(v1, 0.f);
    float m = fmaxf(v0, v1);
#pragma unroll
    for (int o = 16; o; o >>= 1) m = fmaxf(m, __shfl_xor_sync(0xffffffffu, m, o));
    if ((tid & 31) == 0) red[tid >> 5] = m;
    __syncthreads();
    m = red[0];
#pragma unroll
    for (int i = 1; i < 8; i++) m = fmaxf(m, red[i]);
    float e0 = expf(v0 - m), e1 = expf(v1 - m);
    float s = e0 + e1;
#pragma unroll
    for (int o = 16; o; o >>= 1) s += __shfl_xor_sync(0xffffffffu, s, o);
    __syncthreads();
    if ((tid & 31) == 0) red[tid >> 5] = s;
    __syncthreads();
    float tot = 0.f;
#pragma unroll
    for (int i = 0; i < 8; i++) tot += red[i];
    float inv = 1.f / tot;
    float* dst = DYN ? (g_Ad + (size_t)b * NN * NN + (size_t)row * NN) : (g_A + row * NN);
    dst[c0] = __uint_as_float(tf32cvt(e0 * inv));
    dst[c1] = __uint_as_float(tf32cvt(e1 * inv));
}

// ---------------- hypernetwork: E_dyn = NE + h @ hW + hb ----------------
__global__ void hyper_kernel(const float* __restrict__ ne,
                             const float* __restrict__ hW,
                             const float* __restrict__ hb) {
    __shared__ float Ws[HH * EE];
    int tid = threadIdx.x;
    for (int i = tid; i < HH * EE; i += 256) Ws[i] = hW[i];
    __syncthreads();
    int lr = tid >> 4, e = tid & 15;
    int row = blockIdx.x * 16 + lr;
    if (e < EE) {
        float acc = hb[e];
        const float* hp = g_h + row * HH;
#pragma unroll
        for (int j = 0; j < HH; j++) acc += hp[j] * Ws[j * EE + e];
        int n = row & (NN - 1);
        g_Edyn[row * EE + e] = ne[n * EE + e] + acc;
    }
}

// ---------------- graph apply, tf32 mma, lead folded into k-loop ----------------
// grid (4, BATCH). Block: 128 rows x 64 cols. 8 warps, warp tile 32x32.
// Lead (L cols): computed from the same As tiles, per thread 1 row-half.
// LMODE 0: lead = x(t); 1: lead = [go, ycov(t)]; 2: lead = g_y1
#define AS 36
#define XS 72
template <bool BA, int L, int LMODE>
__global__ void __launch_bounds__(256) ga_mma(int xsel, int ysel, int osel,
                                              float alpha, float beta,
                                              const float* __restrict__ xsrc, int t,
                                              int leaddst) {
    __shared__ float As[128 * AS];
    __shared__ float Xs[32 * XS];
    __shared__ float xsl[L > 0 ? NN * L : 1];
    int b = blockIdx.y;
    int i0 = blockIdx.x * 128;
    int tid = threadIdx.x;
    const float* Ab = (BA ? (g_Ad + (size_t)b * NN * NN) : g_A) + (size_t)i0 * NN;
    const float* Xb = buf64(xsel) + b * NN * HH;
    const float* Yb = (ysel >= 0) ? (buf64(ysel) + b * NN * HH) : nullptr;
    float* Ob = buf64(osel) + b * NN * HH;

    if (L > 0) {
        for (int i = tid; i < NN * L; i += 256) {
            int k = i / L, c = i - (i / L) * L;
            float v;
            if (LMODE == 0) v = xsrc[(b * TSTEPS + t) * NN + k];
            else if (LMODE == 1) v = (c == 0) ? g_go[b * NN + k] : xsrc[(b * TSTEPS + t) * NN + k];
            else v = g_y1[(b * NN + k) * L + c];
            xsl[i] = v;
        }
    }

    int lane = tid & 31, w = tid >> 5;
    int gid = lane >> 2, tq = lane & 3;
    int R = (w & 3) * 32;
    int CH = (w >> 2) * 32;
    float acc[2][4][4];
#pragma unroll
    for (int rt = 0; rt < 2; rt++)
#pragma unroll
        for (int j = 0; j < 4; j++)
#pragma unroll
            for (int c = 0; c < 4; c++) acc[rt][j][c] = 0.f;

    // lead accumulators: thread handles row (tid>>1), k-half (tid&1)
    int lrow = tid >> 1, lhalf = tid & 1;
    float lacc0 = 0.f, lacc1 = 0.f;

    for (int k0 = 0; k0 < NN; k0 += 32) {
        // As: 128x32 (pre-rounded tf32 floats), float4 copies
#pragma unroll
        for (int q = 0; q < 4; q++) {
            int idx = tid + q * 256;
            int r = idx >> 3, c4 = idx & 7;
            float4 v = *(const float4*)&Ab[(size_t)r * NN + k0 + c4 * 4];
            *(float4*)&As[r * AS + c4 * 4] = v;
        }
        // Xs: 32x64 with tf32 cvt
#pragma unroll
        for (int q = 0; q < 2; q++) {
            int idx = tid + q * 256;
            int k = idx >> 4, n4 = idx & 15;
            float4 v = *(const float4*)&Xb[(k0 + k) * HH + n4 * 4];
            v.x = __uint_as_float(tf32cvt(v.x));
            v.y = __uint_as_float(tf32cvt(v.y));
            v.z = __uint_as_float(tf32cvt(v.z));
            v.w = __uint_as_float(tf32cvt(v.w));
            *(float4*)&Xs[k * XS + n4 * 4] = v;
        }
        __syncthreads();
#pragma unroll
        for (int ks = 0; ks < 4; ks++) {
            int kb = ks * 8;
            uint32_t b0[4], b1[4];
#pragma unroll
            for (int j = 0; j < 4; j++) {
                int nb = CH + j * 8;
                b0[j] = __float_as_uint(Xs[(kb + tq) * XS + nb + gid]);
                b1[j] = __float_as_uint(Xs[(kb + tq + 4) * XS + nb + gid]);
            }
#pragma unroll
            for (int rt = 0; rt < 2; rt++) {
                int Rr = R + rt * 16;
                uint32_t a0 = __float_as_uint(As[(Rr + gid) * AS + kb + tq]);
                uint32_t a1 = __float_as_uint(As[(Rr + gid + 8) * AS + kb + tq]);
                uint32_t a2 = __float_as_uint(As[(Rr + gid) * AS + kb + tq + 4]);
                uint32_t a3 = __float_as_uint(As[(Rr + gid + 8) * AS + kb + tq + 4]);
#pragma unroll
                for (int j = 0; j < 4; j++)
                    mma_tf32(acc[rt][j], a0, a1, a2, a3, b0[j], b1[j]);
            }
        }
        if (L > 0) {
#pragma unroll
            for (int j = 0; j < 16; j++) {
                int k = lhalf * 16 + j;
                float a = As[lrow * AS + k];
                lacc0 += a * xsl[(k0 + k) * L];
                if (L == 2) lacc1 += a * xsl[(k0 + k) * L + 1];
            }
        }
        __syncthreads();
    }

    if (L > 0) {
        lacc0 += __shfl_xor_sync(0xffffffffu, lacc0, 1);
        if (L == 2) lacc1 += __shfl_xor_sync(0xffffffffu, lacc1, 1);
        if (lhalf == 0) {
            float* dst = leaddst ? g_y2 : g_y1;
            dst[(b * NN + i0 + lrow) * L] = lacc0;
            if (L == 2) dst[(b * NN + i0 + lrow) * L + 1] = lacc1;
        }
    }

#pragma unroll
    for (int rt = 0; rt < 2; rt++) {
#pragma unroll
        for (int j = 0; j < 4; j++) {
            int col = CH + j * 8 + 2 * tq;
            int row0 = i0 + R + rt * 16 + gid;
            int row1 = row0 + 8;
            int o0 = row0 * HH + col;
            int o1 = row1 * HH + col;
            float2 v0 = make_float2(alpha * acc[rt][j][0], alpha * acc[rt][j][1]);
            float2 v1 = make_float2(alpha * acc[rt][j][2], alpha * acc[rt][j][3]);
            if (Yb) {
                float2 y0 = *(const float2*)&Yb[o0];
                float2 y1 = *(const float2*)&Yb[o1];
                v0.x += beta * y0.x; v0.y += beta * y0.y;
                v1.x += beta * y1.x; v1.y += beta * y1.y;
            }
            *(float2*)&Ob[o0] = v0;
            *(float2*)&Ob[o1] = v1;
        }
    }
}

// ---------------- Xs assembly helper (shared by gate/upd) ----------------
template <int CIN, bool ENC, bool UPD>
__device__ __forceinline__ void load_xs(float* Xs, int r0, const float* __restrict__ xsrc, int t) {
    constexpr int K = 3 * CIN;
    constexpr int L = CIN - HH;
    int tid = threadIdx.x;
    for (int i = tid; i < 32 * K; i += 256) {
        int r = i / K, k = i - r * K;
        int seg = k / CIN, c = k - seg * CIN;
        int row = r0 + r, b = row >> 9, n = row & (NN - 1);
        float v;
        if (c < L) {
            float x0;
            if (ENC) x0 = xsrc[(b * TSTEPS + t) * NN + n];
            else x0 = (c == 0) ? g_go[row] : xsrc[(b * TSTEPS + t) * NN + n];
            if (seg == 0) v = x0;
            else if (seg == 1) v = g_y1[row * L + c];
            else v = 2.f * g_y2[row * L + c] - x0;
        } else {
            int cm = c - L;
            const float* src = (seg == 0) ? (UPD ? g_zh : g_h) : (seg == 1) ? g_u1m : g_u2m;
            v = src[row * HH + cm];
        }
        Xs[i] = v;
    }
}

// ---------------- gate: zr = sigmoid(X @ W + b); zh = z*h; r saved ----------------
template <int CIN, bool ENC>
__global__ void gate_kernel(const float* __restrict__ W, const float* __restrict__ bias,
                            const float* __restrict__ xsrc, int t) {
    constexpr int K = 3 * CIN;
    __shared__ float Xs[32 * K];
    __shared__ float Ws[32 * 128];
    int r0 = blockIdx.x * 32;
    int tid = threadIdx.x;
    load_xs<CIN, ENC, false>(Xs, r0, xsrc, t);
    int j = tid & 63, rg = tid >> 6;
    float acc[8][2];
#pragma unroll
    for (int i = 0; i < 8; i++) { acc[i][0] = 0.f; acc[i][1] = 0.f; }
    for (int k0 = 0; k0 < K; k0 += 32) {
        int kt = min(32, K - k0);
        __syncthreads();
        for (int l = tid; l < kt * 128; l += 256) Ws[l] = W[k0 * 128 + l];
        __syncthreads();
        for (int kk = 0; kk < kt; kk++) {
            float w0 = Ws[kk * 128 + j];
            float w1 = Ws[kk * 128 + j + 64];
#pragma unroll
            for (int i = 0; i < 8; i++) {
                float xv = Xs[(rg + 4 * i) * K + k0 + kk];
                acc[i][0] += xv * w0;
                acc[i][1] += xv * w1;
            }
        }
    }
    float b0 = bias[j], b1 = bias[j + 64];
#pragma unroll
    for (int i = 0; i < 8; i++) {
        int row = r0 + rg + 4 * i;
        float z = 1.f / (1.f + expf(-(acc[i][0] + b0)));
        float rr = 1.f / (1.f + expf(-(acc[i][1] + b1)));
        g_zh[row * HH + j] = z * g_h[row * HH + j];
        g_r[row * HH + j] = rr;
    }
}

// ---------------- update: hc = tanh(X @ W + b); h = r*h + (1-r)*hc; (dec) go = h@pW+pb ----------------
template <int CIN, bool DEC>
__global__ void upd_kernel(const float* __restrict__ W, const float* __restrict__ bias,
                           const float* __restrict__ projW, const float* __restrict__ projb,
                           float* __restrict__ out, const float* __restrict__ xsrc, int t) {
    constexpr int K = 3 * CIN;
    __shared__ float Xs[32 * K];
    __shared__ float Ws[32 * 64];
    int r0 = blockIdx.x * 32;
    int tid = threadIdx.x;
    load_xs<CIN, !DEC, true>(Xs, r0, xsrc, t);
    int j = tid & 31, rg = tid >> 5;
    float acc[4][2];
#pragma unroll
    for (int i = 0; i < 4; i++) { acc[i][0] = 0.f; acc[i][1] = 0.f; }
    for (int k0 = 0; k0 < K; k0 += 32) {
        int kt = min(32, K - k0);
        __syncthreads();
        for (int l = tid; l < kt * 64; l += 256) Ws[l] = W[k0 * 64 + l];
        __syncthreads();
        for (int kk = 0; kk < kt; kk++) {
            float w0 = Ws[kk * 64 + j];
            float w1 = Ws[kk * 64 + j + 32];
#pragma unroll
            for (int i = 0; i < 4; i++) {
                float xv = Xs[(rg + 8 * i) * K + k0 + kk];
                acc[i][0] += xv * w0;
                acc[i][1] += xv * w1;
            }
        }
    }
    float b0 = bias[j], b1 = bias[j + 32];
    float pw0 = DEC ? projW[j] : 0.f;
    float pw1 = DEC ? projW[j + 32] : 0.f;
#pragma unroll
    for (int i = 0; i < 4; i++) {
        int row = r0 + rg + 8 * i;
        float hc0 = tanhf(acc[i][0] + b0);
        float hc1 = tanhf(acc[i][1] + b1);
        float rr0 = g_r[row * HH + j], rr1 = g_r[row * HH + j + 32];
        float h0 = g_h[row * HH + j], h1 = g_h[row * HH + j + 32];
        float hn0 = rr0 * h0 + (1.f - rr0) * hc0;
        float hn1 = rr1 * h1 + (1.f - rr1) * hc1;
        g_h[row * HH + j] = hn0;
        g_h[row * HH + j + 32] = hn1;
        if (DEC) {
            float p = hn0 * pw0 + hn1 * pw1;
#pragma unroll
            for (int o = 16; o; o >>= 1) p += __shfl_xor_sync(0xffffffffu, p, o);
            if (j == 0) {
                float go = p + projb[0];
                g_go[row] = go;
                int b = row >> 9, n = row & (NN - 1);
                out[(b * TSTEPS + t) * NN + n] = go;
            }
        }
    }
}

#define SEL_H 0
#define SEL_ZH 1
#define SEL_U1 2
#define SEL_U2 3

// ---------------- launch ----------------
extern "C" void kernel_launch(void* const* d_in, const int* in_sizes, int n_in,
                              void* d_out, int out_size) {
    const float* x    = (const float*)d_in[0];
    const float* ycov = (const float*)d_in[1];
    const float* ne   = (const float*)d_in[2];
    const float* egW  = (const float*)d_in[3];
    const float* egb  = (const float*)d_in[4];
    const float* euW  = (const float*)d_in[5];
    const float* eub  = (const float*)d_in[6];
    const float* dgW  = (const float*)d_in[7];
    const float* dgb  = (const float*)d_in[8];
    const float* duW  = (const float*)d_in[9];
    const float* dub  = (const float*)d_in[10];
    const float* pW   = (const float*)d_in[11];
    const float* pb   = (const float*)d_in[12];
    const float* hW   = (const float*)d_in[13];
    const float* hb   = (const float*)d_in[14];
    float* out = (float*)d_out;

    zero_state<<<(BATCH * NN * HH + 255) / 256, 256>>>();
    graph_build<false><<<NN, 256>>>(ne);

    dim3 g4(4, BATCH);
    // encoder
    for (int t = 0; t < TSTEPS; t++) {
        ga_mma<false, 1, 0><<<g4, 256>>>(SEL_H, -1, SEL_U1, 1.f, 0.f, x, t, 0);      // u1=A@h ; y1=A@x
        ga_mma<false, 1, 2><<<g4, 256>>>(SEL_U1, SEL_H, SEL_U2, 2.f, -1.f, x, t, 1); // u2    ; y2=A@y1
        gate_kernel<65, true><<<BATCH * NN / 32, 256>>>(egW, egb, x, t);
        ga_mma<false, 0, 0><<<g4, 256>>>(SEL_ZH, -1, SEL_U1, 1.f, 0.f, nullptr, 0, 0);
        ga_mma<false, 0, 0><<<g4, 256>>>(SEL_U1, SEL_ZH, SEL_U2, 2.f, -1.f, nullptr, 0, 0);
        upd_kernel<65, false><<<BATCH * NN / 32, 256>>>(euW, eub, nullptr, nullptr, nullptr, x, t);
    }
    // dynamic graph
    hyper_kernel<<<BATCH * NN / 16, 256>>>(ne, hW, hb);
    graph_build<true><<<BATCH * NN, 256>>>(nullptr);
    // decoder
    for (int t = 0; t < TSTEPS; t++) {
        ga_mma<true, 2, 1><<<g4, 256>>>(SEL_H, -1, SEL_U1, 1.f, 0.f, ycov, t, 0);
        ga_mma<true, 2, 2><<<g4, 256>>>(SEL_U1, SEL_H, SEL_U2, 2.f, -1.f, ycov, t, 1);
        gate_kernel<66, false><<<BATCH * NN / 32, 256>>>(dgW, dgb, ycov, t);
        ga_mma<true, 0, 0><<<g4, 256>>>(SEL_ZH, -1, SEL_U1, 1.f, 0.f, nullptr, 0, 0);
        ga_mma<true, 0, 0><<<g4, 256>>>(SEL_U1, SEL_ZH, SEL_U2, 2.f, -1.f, nullptr, 0, 0);
        upd_kernel<66, true><<<BATCH * NN / 32, 256>>>(duW, dub, pW, pb, out, ycov, t);
    }
}

// round 5
// speedup vs baseline: 2.2208x; 1.0750x over previous
#include <cuda_runtime.h>
#include <math.h>
#include <stdint.h>

#define BATCH 32
#define TSTEPS 12
#define NN 512
#define HH 64
#define EE 10

// ---------------- device state (no allocations allowed) ----------------
__device__ float g_A[NN * NN];                // static graph (tf32-rounded)
__device__ float g_Ad[BATCH * NN * NN];       // dynamic graphs (tf32-rounded)
__device__ float g_h[BATCH * NN * HH];        // GRU state
__device__ float g_zh[BATCH * NN * HH];       // z * state
__device__ float g_r[BATCH * NN * HH];        // reset gate
__device__ float g_u1m[BATCH * NN * HH];      // A @ main
__device__ float g_u2m[BATCH * NN * HH];      // 2A@u1 - main
__device__ float g_y1[BATCH * NN * 2];        // A @ lead
__device__ float g_y2[BATCH * NN * 2];        // A @ y1
__device__ float g_Edyn[BATCH * NN * EE];     // dynamic embeddings
__device__ float g_go[BATCH * NN];            // decoder output feedback

__device__ __forceinline__ float* buf64(int s) {
    switch (s) {
        case 0: return g_h;
        case 1: return g_zh;
        case 2: return g_u1m;
        default: return g_u2m;
    }
}

__device__ __forceinline__ uint32_t tf32cvt(float x) {
    uint32_t r;
    asm("cvt.rna.tf32.f32 %0, %1;" : "=r"(r) : "f"(x));
    return r;
}

__device__ __forceinline__ void mma_tf32(float* d, uint32_t a0, uint32_t a1, uint32_t a2,
                                         uint32_t a3, uint32_t b0, uint32_t b1) {
    asm volatile(
        "mma.sync.aligned.m16n8k8.row.col.f32.tf32.tf32.f32 "
        "{%0,%1,%2,%3},{%4,%5,%6,%7},{%8,%9},{%0,%1,%2,%3};"
        : "+f"(d[0]), "+f"(d[1]), "+f"(d[2]), "+f"(d[3])
        : "r"(a0), "r"(a1), "r"(a2), "r"(a3), "r"(b0), "r"(b1));
}

__device__ __forceinline__ void cp_async16(uint32_t smem, const void* gmem) {
    asm volatile("cp.async.cg.shared.global [%0], [%1], 16;" :: "r"(smem), "l"(gmem));
}
__device__ __forceinline__ void cp_commit() { asm volatile("cp.async.commit_group;"); }
__device__ __forceinline__ void cp_wait0() { asm volatile("cp.async.wait_group 0;"); }

// ---------------- init ----------------
__global__ void zero_state() {
    int i = blockIdx.x * 256 + threadIdx.x;
    if (i < BATCH * NN * HH) g_h[i] = 0.f;
    if (i < BATCH * NN) g_go[i] = 0.f;
}

// ---------------- graph build: row of softmax(relu(E E^T)), stored tf32-rounded ----------------
template <bool DYN>
__global__ void graph_build(const float* __restrict__ emb) {
    __shared__ float Es[NN * EE];
    __shared__ float red[8];
    int blk = blockIdx.x;
    int b = DYN ? (blk >> 9) : 0;
    int row = blk & (NN - 1);
    const float* E = DYN ? (g_Edyn + b * NN * EE) : emb;
    int tid = threadIdx.x;
    for (int i = tid; i < NN * EE; i += 256) Es[i] = E[i];
    __syncthreads();
    float er[EE];
#pragma unroll
    for (int j = 0; j < EE; j++) er[j] = Es[row * EE + j];
    float v0 = 0.f, v1 = 0.f;
    int c0 = tid, c1 = tid + 256;
#pragma unroll
    for (int j = 0; j < EE; j++) {
        v0 += er[j] * Es[c0 * EE + j];
        v1 += er[j] * Es[c1 * EE + j];
    }
    v0 = fmaxf(v0, 0.f);
    v1 = fmaxf(v1, 0.f);
    float m = fmaxf(v0, v1);
#pragma unroll
    for (int o = 16; o; o >>= 1) m = fmaxf(m, __shfl_xor_sync(0xffffffffu, m, o));
    if ((tid & 31) == 0) red[tid >> 5] = m;
    __syncthreads();
    m = red[0];
#pragma unroll
    for (int i = 1; i < 8; i++) m = fmaxf(m, red[i]);
    float e0 = expf(v0 - m), e1 = expf(v1 - m);
    float s = e0 + e1;
#pragma unroll
    for (int o = 16; o; o >>= 1) s += __shfl_xor_sync(0xffffffffu, s, o);
    __syncthreads();
    if ((tid & 31) == 0) red[tid >> 5] = s;
    __syncthreads();
    float tot = 0.f;
#pragma unroll
    for (int i = 0; i < 8; i++) tot += red[i];
    float inv = 1.f / tot;
    float* dst = DYN ? (g_Ad + (size_t)b * NN * NN + (size_t)row * NN) : (g_A + row * NN);
    dst[c0] = __uint_as_float(tf32cvt(e0 * inv));
    dst[c1] = __uint_as_float(tf32cvt(e1 * inv));
}

// ---------------- hypernetwork: E_dyn = NE + h @ hW + hb ----------------
__global__ void hyper_kernel(const float* __restrict__ ne,
                             const float* __restrict__ hW,
                             const float* __restrict__ hb) {
    __shared__ float Ws[HH * EE];
    int tid = threadIdx.x;
    for (int i = tid; i < HH * EE; i += 256) Ws[i] = hW[i];
    __syncthreads();
    int lr = tid >> 4, e = tid & 15;
    int row = blockIdx.x * 16 + lr;
    if (e < EE) {
        float acc = hb[e];
        const float* hp = g_h + row * HH;
#pragma unroll
        for (int j = 0; j < HH; j++) acc += hp[j] * Ws[j * EE + e];
        int n = row & (NN - 1);
        g_Edyn[row * EE + e] = ne[n * EE + e] + acc;
    }
}

// ---------------- graph apply, tf32 mma, double-buffered cp.async pipeline ----------------
// grid (8, BATCH), 128 threads. Block: 64 rows x 64 cols. 4 warps, warp tile 32x32.
// Lead (L cols) folded into k-loop from the same As tiles.
// LMODE 0: lead = x(t); 1: lead = [go, ycov(t)]; 2: lead = g_y1
#define AS 36
#define XS 72
template <bool BA, int L, int LMODE>
__global__ void __launch_bounds__(128) ga_mma(int xsel, int ysel, int osel,
                                              float alpha, float beta,
                                              const float* __restrict__ xsrc, int t,
                                              int leaddst) {
    __shared__ float As[2][64 * AS];
    __shared__ float Xs[2][32 * XS];
    __shared__ float xsl[L > 0 ? NN * L : 1];
    int b = blockIdx.y;
    int i0 = blockIdx.x * 64;
    int tid = threadIdx.x;
    const float* Ab = (BA ? (g_Ad + (size_t)b * NN * NN) : g_A) + (size_t)i0 * NN;
    const float* Xb = buf64(xsel) + b * NN * HH;
    const float* Yb = (ysel >= 0) ? (buf64(ysel) + b * NN * HH) : nullptr;
    float* Ob = buf64(osel) + b * NN * HH;

    if (L > 0) {
        for (int i = tid; i < NN * L; i += 128) {
            int k = i / L, c = i - (i / L) * L;
            float v;
            if (LMODE == 0) v = xsrc[(b * TSTEPS + t) * NN + k];
            else if (LMODE == 1) v = (c == 0) ? g_go[b * NN + k] : xsrc[(b * TSTEPS + t) * NN + k];
            else v = g_y1[(b * NN + k) * L + c];
            xsl[i] = v;
        }
    }

    // per-thread A-copy geometry: 512 16B chunks, 4 per thread
    int ar = 0, ac4 = 0;
    {
        // precompute bases for q=0 chunk; strides handled in loop
    }
    // per-thread X geometry: 512 float4, 4 per thread
    float4 xr[4];

    // ---- prologue: stage k0 = 0 ----
#pragma unroll
    for (int q = 0; q < 4; q++) {
        int idx = tid + q * 128;
        int r = idx >> 3, c4 = idx & 7;
        uint32_t s = (uint32_t)__cvta_generic_to_shared(&As[0][r * AS + c4 * 4]);
        cp_async16(s, &Ab[(size_t)r * NN + c4 * 4]);
    }
    cp_commit();
#pragma unroll
    for (int q = 0; q < 4; q++) {
        int idx = tid + q * 128;
        int k = idx >> 4, n4 = idx & 15;
        xr[q] = *(const float4*)&Xb[k * HH + n4 * 4];
    }
#pragma unroll
    for (int q = 0; q < 4; q++) {
        int idx = tid + q * 128;
        int k = idx >> 4, n4 = idx & 15;
        float4 v = xr[q];
        v.x = __uint_as_float(tf32cvt(v.x));
        v.y = __uint_as_float(tf32cvt(v.y));
        v.z = __uint_as_float(tf32cvt(v.z));
        v.w = __uint_as_float(tf32cvt(v.w));
        *(float4*)&Xs[0][k * XS + n4 * 4] = v;
    }
    cp_wait0();
    __syncthreads();

    int lane = tid & 31, w = tid >> 5;
    int gid = lane >> 2, tq = lane & 3;
    int R = (w & 1) * 32;
    int CH = (w >> 1) * 32;
    float acc[2][4][4];
#pragma unroll
    for (int rt = 0; rt < 2; rt++)
#pragma unroll
        for (int j = 0; j < 4; j++)
#pragma unroll
            for (int c = 0; c < 4; c++) acc[rt][j][c] = 0.f;

    int lrow = tid >> 1, lhalf = tid & 1;
    float lacc0 = 0.f, lacc1 = 0.f;

    for (int it = 0; it < 16; it++) {
        int buf = it & 1, nxt = buf ^ 1;
        int k0n = (it + 1) * 32;
        if (it < 15) {
            // issue next A tile
#pragma unroll
            for (int q = 0; q < 4; q++) {
                int idx = tid + q * 128;
                int r = idx >> 3, c4 = idx & 7;
                uint32_t s = (uint32_t)__cvta_generic_to_shared(&As[nxt][r * AS + c4 * 4]);
                cp_async16(s, &Ab[(size_t)r * NN + k0n + c4 * 4]);
            }
            cp_commit();
            // fetch next X tile into regs
#pragma unroll
            for (int q = 0; q < 4; q++) {
                int idx = tid + q * 128;
                int k = idx >> 4, n4 = idx & 15;
                xr[q] = *(const float4*)&Xb[(k0n + k) * HH + n4 * 4];
            }
        }
        // ---- compute on buf ----
        const float* Ac = As[buf];
        const float* Xc = Xs[buf];
#pragma unroll
        for (int ks = 0; ks < 4; ks++) {
            int kb = ks * 8;
            uint32_t b0[4], b1[4];
#pragma unroll
            for (int j = 0; j < 4; j++) {
                int nb = CH + j * 8;
                b0[j] = __float_as_uint(Xc[(kb + tq) * XS + nb + gid]);
                b1[j] = __float_as_uint(Xc[(kb + tq + 4) * XS + nb + gid]);
            }
#pragma unroll
            for (int rt = 0; rt < 2; rt++) {
                int Rr = R + rt * 16;
                uint32_t a0 = __float_as_uint(Ac[(Rr + gid) * AS + kb + tq]);
                uint32_t a1 = __float_as_uint(Ac[(Rr + gid + 8) * AS + kb + tq]);
                uint32_t a2 = __float_as_uint(Ac[(Rr + gid) * AS + kb + tq + 4]);
                uint32_t a3 = __float_as_uint(Ac[(Rr + gid + 8) * AS + kb + tq + 4]);
#pragma unroll
                for (int j = 0; j < 4; j++)
                    mma_tf32(acc[rt][j], a0, a1, a2, a3, b0[j], b1[j]);
            }
        }
        if (L > 0) {
            int k0 = it * 32;
#pragma unroll
            for (int j = 0; j < 16; j++) {
                int k = lhalf * 16 + j;
                float a = Ac[lrow * AS + k];
                lacc0 += a * xsl[(k0 + k) * L];
                if (L == 2) lacc1 += a * xsl[(k0 + k) * L + 1];
            }
        }
        if (it < 15) {
            // store next X tile (cvt) into nxt buffer
#pragma unroll
            for (int q = 0; q < 4; q++) {
                int idx = tid + q * 128;
                int k = idx >> 4, n4 = idx & 15;
                float4 v = xr[q];
                v.x = __uint_as_float(tf32cvt(v.x));
                v.y = __uint_as_float(tf32cvt(v.y));
                v.z = __uint_as_float(tf32cvt(v.z));
                v.w = __uint_as_float(tf32cvt(v.w));
                *(float4*)&Xs[nxt][k * XS + n4 * 4] = v;
            }
            cp_wait0();
        }
        __syncthreads();
    }

    if (L > 0) {
        lacc0 += __shfl_xor_sync(0xffffffffu, lacc0, 1);
        if (L == 2) lacc1 += __shfl_xor_sync(0xffffffffu, lacc1, 1);
        if (lhalf == 0) {
            float* dst = leaddst ? g_y2 : g_y1;
            dst[(b * NN + i0 + lrow) * L] = lacc0;
            if (L == 2) dst[(b * NN + i0 + lrow) * L + 1] = lacc1;
        }
    }

#pragma unroll
    for (int rt = 0; rt < 2; rt++) {
#pragma unroll
        for (int j = 0; j < 4; j++) {
            int col = CH + j * 8 + 2 * tq;
            int row0 = i0 + R + rt * 16 + gid;
            int row1 = row0 + 8;
            int o0 = row0 * HH + col;
            int o1 = row1 * HH + col;
            float2 v0 = make_float2(alpha * acc[rt][j][0], alpha * acc[rt][j][1]);
            float2 v1 = make_float2(alpha * acc[rt][j][2], alpha * acc[rt][j][3]);
            if (Yb) {
                float2 y0 = *(const float2*)&Yb[o0];
                float2 y1 = *(const float2*)&Yb[o1];
                v0.x += beta * y0.x; v0.y += beta * y0.y;
                v1.x += beta * y1.x; v1.y += beta * y1.y;
            }
            *(float2*)&Ob[o0] = v0;
            *(float2*)&Ob[o1] = v1;
        }
    }
}

// ---------------- Xs assembly helper (shared by gate/upd) ----------------
template <int CIN, bool ENC, bool UPD>
__device__ __forceinline__ void load_xs(float* Xs, int r0, const float* __restrict__ xsrc, int t) {
    constexpr int K = 3 * CIN;
    constexpr int L = CIN - HH;
    int tid = threadIdx.x;
    for (int i = tid; i < 32 * K; i += 256) {
        int r = i / K, k = i - r * K;
        int seg = k / CIN, c = k - seg * CIN;
        int row = r0 + r, b = row >> 9, n = row & (NN - 1);
        float v;
        if (c < L) {
            float x0;
            if (ENC) x0 = xsrc[(b * TSTEPS + t) * NN + n];
            else x0 = (c == 0) ? g_go[row] : xsrc[(b * TSTEPS + t) * NN + n];
            if (seg == 0) v = x0;
            else if (seg == 1) v = g_y1[row * L + c];
            else v = 2.f * g_y2[row * L + c] - x0;
        } else {
            int cm = c - L;
            const float* src = (seg == 0) ? (UPD ? g_zh : g_h) : (seg == 1) ? g_u1m : g_u2m;
            v = src[row * HH + cm];
        }
        Xs[i] = v;
    }
}

// ---------------- gate: zr = sigmoid(X @ W + b); zh = z*h; r saved ----------------
template <int CIN, bool ENC>
__global__ void gate_kernel(const float* __restrict__ W, const float* __restrict__ bias,
                            const float* __restrict__ xsrc, int t) {
    constexpr int K = 3 * CIN;
    __shared__ float Xs[32 * K];
    __shared__ float Ws[32 * 128];
    int r0 = blockIdx.x * 32;
    int tid = threadIdx.x;
    load_xs<CIN, ENC, false>(Xs, r0, xsrc, t);
    int j = tid & 63, rg = tid >> 6;
    float acc[8][2];
#pragma unroll
    for (int i = 0; i < 8; i++) { acc[i][0] = 0.f; acc[i][1] = 0.f; }
    for (int k0 = 0; k0 < K; k0 += 32) {
        int kt = min(32, K - k0);
        __syncthreads();
        for (int l = tid; l < kt * 128; l += 256) Ws[l] = W[k0 * 128 + l];
        __syncthreads();
        for (int kk = 0; kk < kt; kk++) {
            float w0 = Ws[kk * 128 + j];
            float w1 = Ws[kk * 128 + j + 64];
#pragma unroll
            for (int i = 0; i < 8; i++) {
                float xv = Xs[(rg + 4 * i) * K + k0 + kk];
                acc[i][0] += xv * w0;
                acc[i][1] += xv * w1;
            }
        }
    }
    float b0 = bias[j], b1 = bias[j + 64];
#pragma unroll
    for (int i = 0; i < 8; i++) {
        int row = r0 + rg + 4 * i;
        float z = 1.f / (1.f + expf(-(acc[i][0] + b0)));
        float rr = 1.f / (1.f + expf(-(acc[i][1] + b1)));
        g_zh[row * HH + j] = z * g_h[row * HH + j];
        g_r[row * HH + j] = rr;
    }
}

// ---------------- update: hc = tanh(X @ W + b); h = r*h + (1-r)*hc; (dec) go = h@pW+pb ----------------
template <int CIN, bool DEC>
__global__ void upd_kernel(const float* __restrict__ W, const float* __restrict__ bias,
                           const float* __restrict__ projW, const float* __restrict__ projb,
                           float* __restrict__ out, const float* __restrict__ xsrc, int t) {
    constexpr int K = 3 * CIN;
    __shared__ float Xs[32 * K];
    __shared__ float Ws[32 * 64];
    int r0 = blockIdx.x * 32;
    int tid = threadIdx.x;
    load_xs<CIN, !DEC, true>(Xs, r0, xsrc, t);
    int j = tid & 31, rg = tid >> 5;
    float acc[4][2];
#pragma unroll
    for (int i = 0; i < 4; i++) { acc[i][0] = 0.f; acc[i][1] = 0.f; }
    for (int k0 = 0; k0 < K; k0 += 32) {
        int kt = min(32, K - k0);
        __syncthreads();
        for (int l = tid; l < kt * 64; l += 256) Ws[l] = W[k0 * 64 + l];
        __syncthreads();
        for (int kk = 0; kk < kt; kk++) {
            float w0 = Ws[kk * 64 + j];
            float w1 = Ws[kk * 64 + j + 32];
#pragma unroll
            for (int i = 0; i < 4; i++) {
                float xv = Xs[(rg + 8 * i) * K + k0 + kk];
                acc[i][0] += xv * w0;
                acc[i][1] += xv * w1;
            }
        }
    }
    float b0 = bias[j], b1 = bias[j + 32];
    float pw0 = DEC ? projW[j] : 0.f;
    float pw1 = DEC ? projW[j + 32] : 0.f;
#pragma unroll
    for (int i = 0; i < 4; i++) {
        int row = r0 + rg + 8 * i;
        float hc0 = tanhf(acc[i][0] + b0);
        float hc1 = tanhf(acc[i][1] + b1);
        float rr0 = g_r[row * HH + j], rr1 = g_r[row * HH + j + 32];
        float h0 = g_h[row * HH + j], h1 = g_h[row * HH + j + 32];
        float hn0 = rr0 * h0 + (1.f - rr0) * hc0;
        float hn1 = rr1 * h1 + (1.f - rr1) * hc1;
        g_h[row * HH + j] = hn0;
        g_h[row * HH + j + 32] = hn1;
        if (DEC) {
            float p = hn0 * pw0 + hn1 * pw1;
#pragma unroll
            for (int o = 16; o; o >>= 1) p += __shfl_xor_sync(0xffffffffu, p, o);
            if (j == 0) {
                float go = p + projb[0];
                g_go[row] = go;
                int b = row >> 9, n = row & (NN - 1);
                out[(b * TSTEPS + t) * NN + n] = go;
            }
        }
    }
}

#define SEL_H 0
#define SEL_ZH 1
#define SEL_U1 2
#define SEL_U2 3

// ---------------- launch ----------------
extern "C" void kernel_launch(void* const* d_in, const int* in_sizes, int n_in,
                              void* d_out, int out_size) {
    const float* x    = (const float*)d_in[0];
    const float* ycov = (const float*)d_in[1];
    const float* ne   = (const float*)d_in[2];
    const float* egW  = (const float*)d_in[3];
    const float* egb  = (const float*)d_in[4];
    const float* euW  = (const float*)d_in[5];
    const float* eub  = (const float*)d_in[6];
    const float* dgW  = (const float*)d_in[7];
    const float* dgb  = (const float*)d_in[8];
    const float* duW  = (const float*)d_in[9];
    const float* dub  = (const float*)d_in[10];
    const float* pW   = (const float*)d_in[11];
    const float* pb   = (const float*)d_in[12];
    const float* hW   = (const float*)d_in[13];
    const float* hb   = (const float*)d_in[14];
    float* out = (float*)d_out;

    zero_state<<<(BATCH * NN * HH + 255) / 256, 256>>>();
    graph_build<false><<<NN, 256>>>(ne);

    dim3 g8(8, BATCH);
    // encoder
    for (int t = 0; t < TSTEPS; t++) {
        ga_mma<false, 1, 0><<<g8, 128>>>(SEL_H, -1, SEL_U1, 1.f, 0.f, x, t, 0);      // u1=A@h ; y1=A@x
        ga_mma<false, 1, 2><<<g8, 128>>>(SEL_U1, SEL_H, SEL_U2, 2.f, -1.f, x, t, 1); // u2    ; y2=A@y1
        gate_kernel<65, true><<<BATCH * NN / 32, 256>>>(egW, egb, x, t);
        ga_mma<false, 0, 0><<<g8, 128>>>(SEL_ZH, -1, SEL_U1, 1.f, 0.f, nullptr, 0, 0);
        ga_mma<false, 0, 0><<<g8, 128>>>(SEL_U1, SEL_ZH, SEL_U2, 2.f, -1.f, nullptr, 0, 0);
        upd_kernel<65, false><<<BATCH * NN / 32, 256>>>(euW, eub, nullptr, nullptr, nullptr, x, t);
    }
    // dynamic graph
    hyper_kernel<<<BATCH * NN / 16, 256>>>(ne, hW, hb);
    graph_build<true><<<BATCH * NN, 256>>>(nullptr);
    // decoder
    for (int t = 0; t < TSTEPS; t++) {
        ga_mma<true, 2, 1><<<g8, 128>>>(SEL_H, -1, SEL_U1, 1.f, 0.f, ycov, t, 0);
        ga_mma<true, 2, 2><<<g8, 128>>>(SEL_U1, SEL_H, SEL_U2, 2.f, -1.f, ycov, t, 1);
        gate_kernel<66, false><<<BATCH * NN / 32, 256>>>(dgW, dgb, ycov, t);
        ga_mma<true, 0, 0><<<g8, 128>>>(SEL_ZH, -1, SEL_U1, 1.f, 0.f, nullptr, 0, 0);
        ga_mma<true, 0, 0><<<g8, 128>>>(SEL_U1, SEL_ZH, SEL_U2, 2.f, -1.f, nullptr, 0, 0);
        upd_kernel<66, true><<<BATCH * NN / 32, 256>>>(duW, dub, pW, pb, out, ycov, t);
    }
}